// round 1
// baseline (speedup 1.0000x reference)
#include <cuda_runtime.h>

// VolGeoNet trilinear interpolation gather.
// x:            (B, 3) float32
// grid_value:   (65^3, 1) float32
// grid_feature: (65^3, 256) float32
// outputs (concatenated in d_out): out (B,1) then feat (B,256)

#define N_GRID 64
#define N1     65
#define W_FEAT 256

__global__ __launch_bounds__(256, 8)
void trilerp_kernel(const float* __restrict__ x,
                    const float* __restrict__ gval,
                    const float* __restrict__ gfeat,
                    float* __restrict__ out_val,
                    float* __restrict__ out_feat,
                    int B)
{
    const int lane64 = threadIdx.x & 63;                 // which float4 of the 256-wide row
    const int point  = blockIdx.x * 4 + (threadIdx.x >> 6);
    if (point >= B) return;

    // All 64 threads of this point read the same 3 coords (L1 broadcast).
    const float px = x[point * 3 + 0];
    const float py = x[point * 3 + 1];
    const float pz = x[point * 3 + 2];

    const float rx = (px + 1.0f) * 32.0f;
    const float ry = (py + 1.0f) * 32.0f;
    const float rz = (pz + 1.0f) * 32.0f;

    const bool valid = (rx >= 0.0f) & (rx <= 64.0f) &
                       (ry >= 0.0f) & (ry <= 64.0f) &
                       (rz >= 0.0f) & (rz <= 64.0f);

    float4 acc = make_float4(0.0f, 0.0f, 0.0f, 0.0f);
    float  accv = 0.0f;

    if (valid) {
        int ix = min(max(__float2int_rd(rx), 0), N_GRID - 1);
        int iy = min(max(__float2int_rd(ry), 0), N_GRID - 1);
        int iz = min(max(__float2int_rd(rz), 0), N_GRID - 1);

        const float tx = rx - (float)ix;
        const float ty = ry - (float)iy;
        const float tz = rz - (float)iz;

        const int base = (ix * N1 + iy) * N1 + iz;

        const float wx0 = 1.0f - tx, wx1 = tx;
        const float wy0 = 1.0f - ty, wy1 = ty;
        const float wz0 = 1.0f - tz, wz1 = tz;

        float w[8];
        w[0] = wx0 * wy0 * wz0;   // ox=0 oy=0 oz=0
        w[1] = wx0 * wy0 * wz1;   // oz=1
        w[2] = wx0 * wy1 * wz0;   // oy=1
        w[3] = wx0 * wy1 * wz1;
        w[4] = wx1 * wy0 * wz0;   // ox=1
        w[5] = wx1 * wy0 * wz1;
        w[6] = wx1 * wy1 * wz0;
        w[7] = wx1 * wy1 * wz1;

        const int off[8] = {
            0, 1, N1, N1 + 1,
            N1 * N1, N1 * N1 + 1, N1 * N1 + N1, N1 * N1 + N1 + 1
        };

        #pragma unroll
        for (int c = 0; c < 8; c++) {
            const int flat = base + off[c];
            const float wc = w[c];
            const float4 v = __ldg(
                reinterpret_cast<const float4*>(gfeat + (size_t)flat * W_FEAT) + lane64);
            acc.x = fmaf(wc, v.x, acc.x);
            acc.y = fmaf(wc, v.y, acc.y);
            acc.z = fmaf(wc, v.z, acc.z);
            acc.w = fmaf(wc, v.w, acc.w);
            if (lane64 == 0) {
                accv = fmaf(wc, __ldg(gval + flat), accv);
            }
        }
    }

    reinterpret_cast<float4*>(out_feat + (size_t)point * W_FEAT)[lane64] = acc;
    if (lane64 == 0) {
        out_val[point] = accv;
    }
}

extern "C" void kernel_launch(void* const* d_in, const int* in_sizes, int n_in,
                              void* d_out, int out_size)
{
    const float* x     = (const float*)d_in[0];
    const float* gval  = (const float*)d_in[1];
    const float* gfeat = (const float*)d_in[2];

    const int B = in_sizes[0] / 3;

    float* out_val  = (float*)d_out;        // (B, 1)
    float* out_feat = (float*)d_out + B;    // (B, 256)

    const int points_per_block = 4;                 // 256 threads, 64 per point
    const int grid = (B + points_per_block - 1) / points_per_block;
    trilerp_kernel<<<grid, 256>>>(x, gval, gfeat, out_val, out_feat, B);
}

// round 3
// speedup vs baseline: 1.1637x; 1.1637x over previous
#include <cuda_runtime.h>

// VolGeoNet trilinear interpolation gather, with spatial (Morton) point binning
// so the gather kernel walks the grid in cache-friendly order.
//
// x:            (B, 3) float32
// grid_value:   (65^3, 1) float32
// grid_feature: (65^3, 256) float32
// outputs (concatenated in d_out): out (B,1) then feat (B,256)

#define N_GRID 64
#define N1     65
#define W_FEAT 256
#define B_MAX  262144
#define NBINS  32768      // 32^3 bins of 2x2x2 cells, Morton ordered

__device__ int g_counts[NBINS];
__device__ int g_offsets[NBINS];
__device__ int g_cursor[NBINS];
__device__ int g_perm[B_MAX];

__device__ __forceinline__ unsigned spread3(unsigned v) {
    // spread low 10 bits of v to every 3rd bit
    v &= 0x3FF;
    v = (v | (v << 16)) & 0x30000FF;
    v = (v | (v << 8))  & 0x300F00F;
    v = (v | (v << 4))  & 0x30C30C3;
    v = (v | (v << 2))  & 0x9249249;
    return v;
}

__device__ __forceinline__ int point_bin(const float* __restrict__ x, int p) {
    const float rx = (x[p * 3 + 0] + 1.0f) * 32.0f;
    const float ry = (x[p * 3 + 1] + 1.0f) * 32.0f;
    const float rz = (x[p * 3 + 2] + 1.0f) * 32.0f;
    int ix = min(max(__float2int_rd(rx), 0), N_GRID - 1);
    int iy = min(max(__float2int_rd(ry), 0), N_GRID - 1);
    int iz = min(max(__float2int_rd(rz), 0), N_GRID - 1);
    // 2^3-cell bins -> 5 bits per axis, Morton interleave -> 15-bit bin id
    unsigned bx = (unsigned)(ix >> 1), by = (unsigned)(iy >> 1), bz = (unsigned)(iz >> 1);
    return (int)(spread3(bx) | (spread3(by) << 1) | (spread3(bz) << 2));
}

__global__ void zero_counts_kernel() {
    int i = blockIdx.x * blockDim.x + threadIdx.x;
    if (i < NBINS) g_counts[i] = 0;
}

__global__ void hist_kernel(const float* __restrict__ x, int B) {
    int p = blockIdx.x * blockDim.x + threadIdx.x;
    if (p >= B) return;
    atomicAdd(&g_counts[point_bin(x, p)], 1);
}

// Single-block exclusive scan over NBINS = 32768 = 1024 threads x 32 elems.
__global__ __launch_bounds__(1024)
void scan_kernel() {
    __shared__ int partial[1024];
    const int t = threadIdx.x;
    const int base = t * 32;

    int local[32];
    int s = 0;
    #pragma unroll
    for (int i = 0; i < 32; i++) {
        local[i] = g_counts[base + i];
        s += local[i];
    }
    partial[t] = s;
    __syncthreads();

    // Hillis-Steele inclusive scan of 1024 partials
    for (int off = 1; off < 1024; off <<= 1) {
        int v = (t >= off) ? partial[t - off] : 0;
        __syncthreads();
        partial[t] += v;
        __syncthreads();
    }

    int excl = (t > 0) ? partial[t - 1] : 0;
    #pragma unroll
    for (int i = 0; i < 32; i++) {
        g_offsets[base + i] = excl;
        g_cursor[base + i]  = excl;
        excl += local[i];
    }
}

__global__ void scatter_kernel(const float* __restrict__ x, int B) {
    int p = blockIdx.x * blockDim.x + threadIdx.x;
    if (p >= B) return;
    int bin = point_bin(x, p);
    int pos = atomicAdd(&g_cursor[bin], 1);
    g_perm[pos] = p;
}

__global__ __launch_bounds__(256, 8)
void trilerp_kernel(const float* __restrict__ x,
                    const float* __restrict__ gval,
                    const float* __restrict__ gfeat,
                    float* __restrict__ out_val,
                    float* __restrict__ out_feat,
                    int B)
{
    const int lane64 = threadIdx.x & 63;                 // which float4 of the row
    const int spos   = blockIdx.x * 4 + (threadIdx.x >> 6);
    if (spos >= B) return;
    const int point = g_perm[spos];                      // broadcast within the 64 threads

    const float px = x[point * 3 + 0];
    const float py = x[point * 3 + 1];
    const float pz = x[point * 3 + 2];

    const float rx = (px + 1.0f) * 32.0f;
    const float ry = (py + 1.0f) * 32.0f;
    const float rz = (pz + 1.0f) * 32.0f;

    const bool valid = (rx >= 0.0f) & (rx <= 64.0f) &
                       (ry >= 0.0f) & (ry <= 64.0f) &
                       (rz >= 0.0f) & (rz <= 64.0f);

    float4 acc = make_float4(0.0f, 0.0f, 0.0f, 0.0f);
    float  accv = 0.0f;

    if (valid) {
        int ix = min(max(__float2int_rd(rx), 0), N_GRID - 1);
        int iy = min(max(__float2int_rd(ry), 0), N_GRID - 1);
        int iz = min(max(__float2int_rd(rz), 0), N_GRID - 1);

        const float tx = rx - (float)ix;
        const float ty = ry - (float)iy;
        const float tz = rz - (float)iz;

        const int base = (ix * N1 + iy) * N1 + iz;

        const float wx0 = 1.0f - tx, wx1 = tx;
        const float wy0 = 1.0f - ty, wy1 = ty;
        const float wz0 = 1.0f - tz, wz1 = tz;

        float w[8];
        w[0] = wx0 * wy0 * wz0;
        w[1] = wx0 * wy0 * wz1;
        w[2] = wx0 * wy1 * wz0;
        w[3] = wx0 * wy1 * wz1;
        w[4] = wx1 * wy0 * wz0;
        w[5] = wx1 * wy0 * wz1;
        w[6] = wx1 * wy1 * wz0;
        w[7] = wx1 * wy1 * wz1;

        const int off[8] = {
            0, 1, N1, N1 + 1,
            N1 * N1, N1 * N1 + 1, N1 * N1 + N1, N1 * N1 + N1 + 1
        };

        #pragma unroll
        for (int c = 0; c < 8; c++) {
            const int flat = base + off[c];
            const float wc = w[c];
            const float4 v = __ldg(
                reinterpret_cast<const float4*>(gfeat + (size_t)flat * W_FEAT) + lane64);
            acc.x = fmaf(wc, v.x, acc.x);
            acc.y = fmaf(wc, v.y, acc.y);
            acc.z = fmaf(wc, v.z, acc.z);
            acc.w = fmaf(wc, v.w, acc.w);
            if (lane64 == 0) {
                accv = fmaf(wc, __ldg(gval + flat), accv);
            }
        }
    }

    // Streaming stores: evict-first so output traffic doesn't pollute the L2
    // working set of grid_feature.
    __stcs(reinterpret_cast<float4*>(out_feat + (size_t)point * W_FEAT) + lane64, acc);
    if (lane64 == 0) {
        __stcs(out_val + point, accv);
    }
}

extern "C" void kernel_launch(void* const* d_in, const int* in_sizes, int n_in,
                              void* d_out, int out_size)
{
    const float* x     = (const float*)d_in[0];
    const float* gval  = (const float*)d_in[1];
    const float* gfeat = (const float*)d_in[2];

    const int B = in_sizes[0] / 3;

    float* out_val  = (float*)d_out;        // (B, 1)
    float* out_feat = (float*)d_out + B;    // (B, 256)

    zero_counts_kernel<<<(NBINS + 255) / 256, 256>>>();
    hist_kernel<<<(B + 255) / 256, 256>>>(x, B);
    scan_kernel<<<1, 1024>>>();
    scatter_kernel<<<(B + 255) / 256, 256>>>(x, B);

    const int points_per_block = 4;                 // 256 threads, 64 per point
    const int grid = (B + points_per_block - 1) / points_per_block;
    trilerp_kernel<<<grid, 256>>>(x, gval, gfeat, out_val, out_feat, B);
}